// round 14
// baseline (speedup 1.0000x reference)
#include <cuda_runtime.h>
#include <cuda_fp16.h>
#include <math.h>
#include <cstdint>

#define B_ 2
#define S_ 2048
#define D_ 1024
#define H_ 16
#define HD_ 64
#define SCALE2 0.1803368801111204f
#define ONESH2 0x3C003C00u

// Scratch (device globals: allocation-free rule)
__device__ __half g_Qh[B_ * H_ * S_ * HD_];
__device__ __half g_Kh[B_ * H_ * S_ * HD_];
__device__ __half g_Vh[B_ * H_ * S_ * HD_];
__device__ __half g_Ch[B_ * S_ * D_];
__device__ __half g_Xh[B_ * S_ * D_];
__device__ __half g_W1h[3 * D_ * D_];
__device__ __half g_W2h[D_ * D_];
// mask bias, fragment-major: word(r, j, t4, nt) at r*1024 + j*32 + t4*8 + nt
__device__ __half g_Bh[S_ * S_];

__device__ __forceinline__ float ex2(float x) {
    float y;
    asm("ex2.approx.f32 %0, %1;" : "=f"(y) : "f"(x));
    return y;
}
__device__ __forceinline__ unsigned ex2h2(unsigned x) {
    unsigned y;
    asm("ex2.approx.f16x2 %0, %1;" : "=r"(y) : "r"(x));
    return y;
}
__device__ __forceinline__ unsigned h2(float a, float b) {
    __half2 h = __floats2half2_rn(a, b);
    return *(unsigned*)&h;
}
__device__ __forceinline__ unsigned hadd2u(unsigned a, unsigned b) {
    __half2 r = __hadd2(*(__half2*)&a, *(__half2*)&b);
    return *(unsigned*)&r;
}
__device__ __forceinline__ void mma_f16(float c[4], unsigned a0, unsigned a1,
                                        unsigned a2, unsigned a3,
                                        unsigned b0, unsigned b1) {
    asm volatile(
        "mma.sync.aligned.m16n8k16.row.col.f32.f16.f16.f32 "
        "{%0,%1,%2,%3}, {%4,%5,%6,%7}, {%8,%9}, {%0,%1,%2,%3};"
        : "+f"(c[0]), "+f"(c[1]), "+f"(c[2]), "+f"(c[3])
        : "r"(a0), "r"(a1), "r"(a2), "r"(a3), "r"(b0), "r"(b1));
}
__device__ __forceinline__ unsigned smem_u32(const void* p) {
    return (unsigned)__cvta_generic_to_shared(p);
}
__device__ __forceinline__ void ldsm4(unsigned r[4], unsigned addr) {
    asm volatile(
        "ldmatrix.sync.aligned.m8n8.x4.shared.b16 {%0,%1,%2,%3}, [%4];"
        : "=r"(r[0]), "=r"(r[1]), "=r"(r[2]), "=r"(r[3]) : "r"(addr));
}
__device__ __forceinline__ void ldsm4t(unsigned r[4], unsigned addr) {
    asm volatile(
        "ldmatrix.sync.aligned.m8n8.x4.trans.shared.b16 {%0,%1,%2,%3}, [%4];"
        : "=r"(r[0]), "=r"(r[1]), "=r"(r[2]), "=r"(r[3]) : "r"(addr));
}
__device__ __forceinline__ void cp16(unsigned dst, const void* src) {
    asm volatile("cp.async.cg.shared.global [%0], [%1], 16;" ::"r"(dst), "l"(src));
}
#define CP_COMMIT() asm volatile("cp.async.commit_group;" ::: "memory")
template <int N>
__device__ __forceinline__ void cp_wait() {
    asm volatile("cp.async.wait_group %0;" ::"n"(N) : "memory");
}

// ---------------------------------------------------------------------------
// mask -> additive fp16 bias (0 / -32768), fragment-major layout.
// Total words = S*S/2 = 2,097,152; 4 words/thread, 256 thr -> 2048 blocks.
__global__ __launch_bounds__(256) void biasprep(const int* __restrict__ mask) {
    int wbase = (blockIdx.x * 256 + threadIdx.x) * 4;
    unsigned wds[4];
#pragma unroll
    for (int q = 0; q < 4; ++q) {
        int wd = wbase + q;
        int r = wd >> 10, rem = wd & 1023;
        int j = rem >> 5, t4 = (rem >> 3) & 3, nt = rem & 7;
        int c = j * 64 + nt * 8 + 2 * t4;
        int m0 = __ldg(mask + (size_t)r * S_ + c);
        int m1 = __ldg(mask + (size_t)r * S_ + c + 1);
        wds[q] = (m0 ? 0u : 0xF800u) | (m1 ? 0u : 0xF8000000u);
    }
    *(uint4*)((unsigned*)g_Bh + wbase) = make_uint4(wds[0], wds[1], wds[2], wds[3]);
}

// single-launch f32 -> f16 convert for x, w_qkv, w_o
__global__ __launch_bounds__(256) void conv_all(const float* __restrict__ x,
                                                const float* __restrict__ w1,
                                                const float* __restrict__ w2) {
    int b = blockIdx.x;
    const float* src;
    __half* dst;
    int base;
    if (b < 2048)      { src = x;  dst = g_Xh;  base = b; }
    else if (b < 3584) { src = w1; dst = g_W1h; base = b - 2048; }
    else               { src = w2; dst = g_W2h; base = b - 3584; }
    int i = (base * 256 + threadIdx.x) * 8;
    float4 v0 = *(const float4*)(src + i);
    float4 v1 = *(const float4*)(src + i + 4);
    uint4 u;
    u.x = h2(v0.x, v0.y); u.y = h2(v0.z, v0.w);
    u.z = h2(v1.x, v1.y); u.w = h2(v1.z, v1.w);
    *(uint4*)(dst + i) = u;
}

// ---------------------------------------------------------------------------
// fp16 tensor-core GEMM, 3-stage cp.async ring (no LDG->reg->STS roundtrip).
// Block 128x128, BK=64 halves, 8 warps (2x4), warp tile 64x32, stride 72.
// Prologue stages k=0,1; per iter: cp_wait -> barrier -> issue k+2 -> 64 mma.
// MODE 0: A=g_Xh, N=3072, scatter half2 into g_Qh/g_Kh/g_Vh (Q pre-scaled).
// MODE 1: A=g_Ch, N=1024, out f32.
// ---------------------------------------------------------------------------
#define GBUF (128 * 72 * 2)   // bytes per stage per operand

template <int MODE>
__device__ __forceinline__ void g_stage(const __half* __restrict__ A,
                                        const __half* __restrict__ W,
                                        int m0, int n0, int kc,
                                        unsigned sA, unsigned sB,
                                        int r0, int seg) {
    const int ko = kc * 64;
#pragma unroll
    for (int i = 0; i < 4; ++i) {
        int row = r0 + i * 32;
        cp16(sA + (row * 72 + seg * 8) * 2, A + (size_t)(m0 + row) * D_ + ko + seg * 8);
        cp16(sB + (row * 72 + seg * 8) * 2, W + (size_t)(n0 + row) * D_ + ko + seg * 8);
    }
    CP_COMMIT();
}

template <int MODE>
__global__ __launch_bounds__(256, 2) void gemm_tc(const __half* __restrict__ A,
                                                  const __half* __restrict__ W,
                                                  const float* __restrict__ bias,
                                                  float* __restrict__ out) {
    extern __shared__ __half shh[];
    // layout: A stages [3][128][72], then B stages [3][128][72]
    const int m0 = blockIdx.y * 128;
    const int n0 = blockIdx.x * 128;
    const int t = threadIdx.x;
    const int w = t >> 5;
    const int lane = t & 31;
    const int g = lane >> 2;
    const int t4 = lane & 3;
    const int wm = (w >> 2) * 64;
    const int wn = (w & 3) * 32;

    const int seg = t & 7;
    const int r0 = t >> 3;

    const unsigned sA = smem_u32(shh);
    const unsigned sB = sA + 3 * GBUF;
    const unsigned aoff = (wm + (lane & 15)) * 144 + (lane >> 4) * 16;
    const unsigned boff = (wn + (lane & 15)) * 144 + (lane >> 4) * 16;

    g_stage<MODE>(A, W, m0, n0, 0, sA, sB, r0, seg);
    g_stage<MODE>(A, W, m0, n0, 1, sA + GBUF, sB + GBUF, r0, seg);

    float acc[4][4][4];
#pragma unroll
    for (int mt = 0; mt < 4; ++mt)
#pragma unroll
        for (int nt = 0; nt < 4; ++nt)
#pragma unroll
            for (int i = 0; i < 4; ++i) acc[mt][nt][i] = 0.0f;

    int cur = 0;
    for (int k0 = 0; k0 < 16; ++k0) {
        if (k0 < 15) cp_wait<1>(); else cp_wait<0>();
        __syncthreads();
        if (k0 + 2 < 16) {
            int nb = cur + 2;
            if (nb >= 3) nb -= 3;
            g_stage<MODE>(A, W, m0, n0, k0 + 2, sA + nb * GBUF, sB + nb * GBUF, r0, seg);
        }
        const unsigned bA = sA + cur * GBUF;
        const unsigned bB = sB + cur * GBUF;
#pragma unroll
        for (int ks = 0; ks < 4; ++ks) {
            unsigned a[4][4];
#pragma unroll
            for (int mt = 0; mt < 4; ++mt)
                ldsm4(a[mt], bA + aoff + mt * 16 * 144 + ks * 32);
#pragma unroll
            for (int p = 0; p < 2; ++p) {
                unsigned bb[4];
                ldsm4(bb, bB + boff + p * 16 * 144 + ks * 32);
#pragma unroll
                for (int mt = 0; mt < 4; ++mt) {
                    mma_f16(acc[mt][2 * p], a[mt][0], a[mt][1], a[mt][2], a[mt][3],
                            bb[0], bb[2]);
                    mma_f16(acc[mt][2 * p + 1], a[mt][0], a[mt][1], a[mt][2], a[mt][3],
                            bb[1], bb[3]);
                }
            }
        }
        cur = (cur == 2) ? 0 : cur + 1;
    }

    // epilogue
#pragma unroll
    for (int mt = 0; mt < 4; ++mt) {
#pragma unroll
        for (int nt = 0; nt < 4; ++nt) {
            int ncol = n0 + wn + nt * 8 + 2 * t4;
            float bx = __ldg(&bias[ncol]);
            float by = __ldg(&bias[ncol + 1]);
#pragma unroll
            for (int rr = 0; rr < 2; ++rr) {
                int m = m0 + wm + mt * 16 + g + rr * 8;
                float vx = acc[mt][nt][rr * 2] + bx;
                float vy = acc[mt][nt][rr * 2 + 1] + by;
                if (MODE == 0) {
                    int bb2 = m >> 11, ss = m & 2047;
                    int h = ncol / 192;
                    int rem = ncol - h * 192;
                    int part = rem >> 6;
                    int d = rem & 63;
                    if (part == 0) { vx *= SCALE2; vy *= SCALE2; }
                    size_t dst = (((size_t)(bb2 * H_ + h)) * S_ + ss) * HD_ + d;
                    __half* dstp = (part == 0 ? g_Qh : (part == 1 ? g_Kh : g_Vh));
                    __half2 hv = __floats2half2_rn(vx, vy);
                    *(__half2*)&dstp[dst] = hv;
                } else {
                    *(float2*)&out[(size_t)m * D_ + ncol] = make_float2(vx, vy);
                }
            }
        }
    }
}

// ---------------------------------------------------------------------------
// Flash attention (unchanged from round 13): fp16 mma, 4-stage cp.async K/V
// ring, register-resident Q fragments, fragment-major mask bias, half-domain
// centering, ex2.f16x2 -> packed PV A-frags, row sums via ones-matrix mma.
// ---------------------------------------------------------------------------
__global__ __launch_bounds__(256, 2) void attn_tc() {
    extern __shared__ __half shh[];
    __half* Qs = shh;                   // [128][72]
    __half* Ks = shh + 128 * 72;        // [4][64][72]
    __half* Vs = Ks + 4 * 64 * 72;      // [4][64][72]

    const int bh = blockIdx.y;
    const int q0 = blockIdx.x * 128;
    const int t = threadIdx.x;
    const int w = t >> 5;
    const int lane = t & 31;
    const int g = lane >> 2;
    const int t4 = lane & 3;

    const size_t base = (size_t)bh * (S_ * HD_);
    const __half* Qg = g_Qh + base;
    const __half* Kg = g_Kh + base;
    const __half* Vg = g_Vh + base;

    const int seg = t & 7;
    const int r0 = t >> 3;

    const unsigned sQ = smem_u32(Qs);
    const unsigned sK = smem_u32(Ks);
    const unsigned sV = smem_u32(Vs);
    const unsigned KBUF = 64 * 72 * 2;
    const unsigned qoff = (w * 16 + (lane & 15)) * 144 + (lane >> 4) * 16;
    const unsigned koff = (lane & 15) * 144 + (lane >> 4) * 16;

    // stage Q
#pragma unroll
    for (int i = 0; i < 4; ++i) {
        int row = r0 + i * 32;
        *(uint4*)&Qs[row * 72 + seg * 8] =
            *(const uint4*)(Qg + (size_t)(q0 + row) * HD_ + seg * 8);
    }
    // cp.async stage K/V tiles 0,1 into ring stages 0,1
#pragma unroll
    for (int tile = 0; tile < 2; ++tile) {
#pragma unroll
        for (int i = 0; i < 2; ++i) {
            int row = r0 + i * 32;
            cp16(sK + tile * KBUF + (row * 72 + seg * 8) * 2,
                 Kg + ((size_t)tile * 64 + row) * HD_ + seg * 8);
            cp16(sV + tile * KBUF + (row * 72 + seg * 8) * 2,
                 Vg + ((size_t)tile * 64 + row) * HD_ + seg * 8);
        }
        CP_COMMIT();
    }
    __syncthreads();

    // Q fragments register-resident (loop-invariant)
    unsigned qa[4][4];
#pragma unroll
    for (int ks = 0; ks < 4; ++ks) ldsm4(qa[ks], sQ + qoff + ks * 32);

    const int qrow0 = q0 + w * 16 + g;
    const int qrow1 = qrow0 + 8;
    const unsigned* bq0 = (const unsigned*)(g_Bh + (size_t)qrow0 * S_) + t4 * 8;
    const unsigned* bq1 = (const unsigned*)(g_Bh + (size_t)qrow1 * S_) + t4 * 8;

    float o[8][4];
#pragma unroll
    for (int nt = 0; nt < 8; ++nt)
#pragma unroll
        for (int i = 0; i < 4; ++i) o[nt][i] = 0.0f;
    float m0s = -INFINITY, m1s = -INFINITY, l0 = 0.0f, l1 = 0.0f;

    for (int jj = 0; jj < 32; jj += 2) {
        cp_wait<0>();
        __syncthreads();
        const unsigned ph = (unsigned)(jj & 2);
#pragma unroll
        for (int u = 0; u < 2; ++u) {
            const int j = jj + u;
            const unsigned bK = sK + (ph + u) * KBUF;
            const unsigned bV = sV + (ph + u) * KBUF;
            if (j + 2 < 32) {
                const __half* Kn = Kg + (size_t)(j + 2) * 64 * HD_;
                const __half* Vn = Vg + (size_t)(j + 2) * 64 * HD_;
                unsigned dK = sK + ((ph + u + 2) & 3) * KBUF;
                unsigned dV = sV + ((ph + u + 2) & 3) * KBUF;
#pragma unroll
                for (int i = 0; i < 2; ++i) {
                    int row = r0 + i * 32;
                    cp16(dK + (row * 72 + seg * 8) * 2, Kn + (size_t)row * HD_ + seg * 8);
                    cp16(dV + (row * 72 + seg * 8) * 2, Vn + (size_t)row * HD_ + seg * 8);
                }
                CP_COMMIT();
            }
            // mask bias (fragment-major): 4 LDG.128
            uint4 ba = __ldg((const uint4*)(bq0 + j * 32));
            uint4 bb4 = __ldg((const uint4*)(bq0 + j * 32 + 4));
            uint4 bc = __ldg((const uint4*)(bq1 + j * 32));
            uint4 bd = __ldg((const uint4*)(bq1 + j * 32 + 4));
            unsigned bw0[8] = {ba.x, ba.y, ba.z, ba.w, bb4.x, bb4.y, bb4.z, bb4.w};
            unsigned bw1[8] = {bc.x, bc.y, bc.z, bc.w, bd.x, bd.y, bd.z, bd.w};

            // S = Q @ K^T
            float sc[8][4];
#pragma unroll
            for (int nt = 0; nt < 8; ++nt)
#pragma unroll
                for (int i = 0; i < 4; ++i) sc[nt][i] = 0.0f;
#pragma unroll
            for (int ks = 0; ks < 4; ++ks) {
#pragma unroll
                for (int p = 0; p < 4; ++p) {
                    unsigned kb[4];
                    ldsm4(kb, bK + koff + p * 16 * 144 + ks * 32);
                    mma_f16(sc[2 * p], qa[ks][0], qa[ks][1], qa[ks][2], qa[ks][3],
                            kb[0], kb[2]);
                    mma_f16(sc[2 * p + 1], qa[ks][0], qa[ks][1], qa[ks][2], qa[ks][3],
                            kb[1], kb[3]);
                }
            }

            // running max over unmasked logits
            float mx0 = -INFINITY, mx1 = -INFINITY;
#pragma unroll
            for (int nt = 0; nt < 8; ++nt) {
                mx0 = fmaxf(mx0, fmaxf(sc[nt][0], sc[nt][1]));
                mx1 = fmaxf(mx1, fmaxf(sc[nt][2], sc[nt][3]));
            }
            mx0 = fmaxf(mx0, __shfl_xor_sync(0xffffffffu, mx0, 1));
            mx0 = fmaxf(mx0, __shfl_xor_sync(0xffffffffu, mx0, 2));
            mx1 = fmaxf(mx1, __shfl_xor_sync(0xffffffffu, mx1, 1));
            mx1 = fmaxf(mx1, __shfl_xor_sync(0xffffffffu, mx1, 2));
            float mn0 = fmaxf(m0s, mx0), mn1 = fmaxf(m1s, mx1);
            float al0 = ex2(m0s - mn0), al1 = ex2(m1s - mn1);
            m0s = mn0; m1s = mn1;
#pragma unroll
            for (int nt = 0; nt < 8; ++nt) {
                o[nt][0] *= al0; o[nt][1] *= al0;
                o[nt][2] *= al1; o[nt][3] *= al1;
            }

            // pack -> +(-mn) -> +bias -> exp, all in half2 domain
            unsigned mneg0 = h2(-mn0, -mn0);
            unsigned mneg1 = h2(-mn1, -mn1);
            unsigned ph_lo[8], ph_hi[8];
#pragma unroll
            for (int nt = 0; nt < 8; ++nt) {
                ph_lo[nt] = ex2h2(hadd2u(hadd2u(h2(sc[nt][0], sc[nt][1]), mneg0), bw0[nt]));
                ph_hi[nt] = ex2h2(hadd2u(hadd2u(h2(sc[nt][2], sc[nt][3]), mneg1), bw1[nt]));
            }

            // row sums via ones-matrix mma
            float rs[4] = {0.0f, 0.0f, 0.0f, 0.0f};
#pragma unroll
            for (int kt = 0; kt < 4; ++kt)
                mma_f16(rs, ph_lo[2 * kt], ph_hi[2 * kt], ph_lo[2 * kt + 1],
                        ph_hi[2 * kt + 1], ONESH2, ONESH2);
            l0 = al0 * l0 + rs[0];
            l1 = al1 * l1 + rs[2];

            // O += P @ V
#pragma unroll
            for (int kt = 0; kt < 4; ++kt) {
                unsigned a0 = ph_lo[2 * kt];
                unsigned a1 = ph_hi[2 * kt];
                unsigned a2 = ph_lo[2 * kt + 1];
                unsigned a3 = ph_hi[2 * kt + 1];
#pragma unroll
                for (int q = 0; q < 4; ++q) {
                    unsigned vb[4];
                    ldsm4t(vb, bV + koff + kt * 16 * 144 + q * 32);
                    mma_f16(o[2 * q], a0, a1, a2, a3, vb[0], vb[1]);
                    mma_f16(o[2 * q + 1], a0, a1, a2, a3, vb[2], vb[3]);
                }
            }
        }
    }

    // epilogue
    const int bb = bh >> 4;
    const int h = bh & 15;
    float inv0 = 1.0f / l0, inv1 = 1.0f / l1;
#pragma unroll
    for (int nt = 0; nt < 8; ++nt) {
        int dcol = h * 64 + nt * 8 + 2 * t4;
        size_t rr0 = ((size_t)bb * S_ + qrow0) * D_ + dcol;
        size_t rr1 = ((size_t)bb * S_ + qrow1) * D_ + dcol;
        __half2 v0 = __floats2half2_rn(o[nt][0] * inv0, o[nt][1] * inv0);
        __half2 v1 = __floats2half2_rn(o[nt][2] * inv1, o[nt][3] * inv1);
        *(__half2*)&g_Ch[rr0] = v0;
        *(__half2*)&g_Ch[rr1] = v1;
    }
}

// ---------------------------------------------------------------------------
extern "C" void kernel_launch(void* const* d_in, const int* in_sizes, int n_in,
                              void* d_out, int out_size) {
    const float* x     = (const float*)d_in[0];
    const int*   mask  = (const int*)d_in[1];
    const float* w_qkv = (const float*)d_in[2];
    const float* b_qkv = (const float*)d_in[3];
    const float* w_o   = (const float*)d_in[4];
    const float* b_o   = (const float*)d_in[5];
    float* out = (float*)d_out;

    const int gemm_smem = 6 * 128 * 72 * 2;              // 110592
    const int attn_smem = (128 * 72 + 8 * 64 * 72) * 2;  // 92160

    cudaFuncSetAttribute(gemm_tc<0>, cudaFuncAttributeMaxDynamicSharedMemorySize, gemm_smem);
    cudaFuncSetAttribute(gemm_tc<1>, cudaFuncAttributeMaxDynamicSharedMemorySize, gemm_smem);
    cudaFuncSetAttribute(attn_tc, cudaFuncAttributeMaxDynamicSharedMemorySize, attn_smem);

    // 0) one-time prep
    biasprep<<<(S_ * S_ / 2) / (4 * 256), 256>>>(mask);   // 2048 blocks
    __half *dXh, *dW1h, *dW2h, *dCh;
    cudaGetSymbolAddress((void**)&dXh, g_Xh);
    cudaGetSymbolAddress((void**)&dW1h, g_W1h);
    cudaGetSymbolAddress((void**)&dW2h, g_W2h);
    cudaGetSymbolAddress((void**)&dCh, g_Ch);
    conv_all<<<4096, 256>>>(x, w_qkv, w_o);

    // 1) QKV projection
    gemm_tc<0><<<dim3(3072 / 128, 4096 / 128), 256, gemm_smem>>>(dXh, dW1h, b_qkv, nullptr);

    // 2) flash attention
    attn_tc<<<dim3(S_ / 128, B_ * H_), 256, attn_smem>>>();

    // 3) output projection
    gemm_tc<1><<<dim3(1024 / 128, 4096 / 128), 256, gemm_smem>>>(dCh, dW2h, b_o, out);
}

// round 15
// speedup vs baseline: 1.0307x; 1.0307x over previous
#include <cuda_runtime.h>
#include <cuda_fp16.h>
#include <math.h>
#include <cstdint>

#define B_ 2
#define S_ 2048
#define D_ 1024
#define H_ 16
#define HD_ 64
#define SCALE2 0.1803368801111204f
#define ONESH2 0x3C003C00u

// Scratch (device globals: allocation-free rule)
__device__ __half g_Qh[B_ * H_ * S_ * HD_];
__device__ __half g_Kh[B_ * H_ * S_ * HD_];
__device__ __half g_Vh[B_ * H_ * S_ * HD_];
__device__ __half g_Ch[B_ * S_ * D_];
__device__ __half g_Xh[B_ * S_ * D_];
__device__ __half g_W1h[3 * D_ * D_];
__device__ __half g_W2h[D_ * D_];
// mask bias, fragment-major: word(r, j, t4, nt) at r*1024 + j*32 + t4*8 + nt
__device__ __half g_Bh[S_ * S_];

__device__ __forceinline__ float ex2(float x) {
    float y;
    asm("ex2.approx.f32 %0, %1;" : "=f"(y) : "f"(x));
    return y;
}
__device__ __forceinline__ unsigned ex2h2(unsigned x) {
    unsigned y;
    asm("ex2.approx.f16x2 %0, %1;" : "=r"(y) : "r"(x));
    return y;
}
__device__ __forceinline__ unsigned h2(float a, float b) {
    __half2 h = __floats2half2_rn(a, b);
    return *(unsigned*)&h;
}
__device__ __forceinline__ unsigned hadd2u(unsigned a, unsigned b) {
    __half2 r = __hadd2(*(__half2*)&a, *(__half2*)&b);
    return *(unsigned*)&r;
}
__device__ __forceinline__ void mma_f16(float c[4], unsigned a0, unsigned a1,
                                        unsigned a2, unsigned a3,
                                        unsigned b0, unsigned b1) {
    asm volatile(
        "mma.sync.aligned.m16n8k16.row.col.f32.f16.f16.f32 "
        "{%0,%1,%2,%3}, {%4,%5,%6,%7}, {%8,%9}, {%0,%1,%2,%3};"
        : "+f"(c[0]), "+f"(c[1]), "+f"(c[2]), "+f"(c[3])
        : "r"(a0), "r"(a1), "r"(a2), "r"(a3), "r"(b0), "r"(b1));
}
__device__ __forceinline__ unsigned smem_u32(const void* p) {
    return (unsigned)__cvta_generic_to_shared(p);
}
__device__ __forceinline__ void ldsm4(unsigned r[4], unsigned addr) {
    asm volatile(
        "ldmatrix.sync.aligned.m8n8.x4.shared.b16 {%0,%1,%2,%3}, [%4];"
        : "=r"(r[0]), "=r"(r[1]), "=r"(r[2]), "=r"(r[3]) : "r"(addr));
}
__device__ __forceinline__ void ldsm4t(unsigned r[4], unsigned addr) {
    asm volatile(
        "ldmatrix.sync.aligned.m8n8.x4.trans.shared.b16 {%0,%1,%2,%3}, [%4];"
        : "=r"(r[0]), "=r"(r[1]), "=r"(r[2]), "=r"(r[3]) : "r"(addr));
}
__device__ __forceinline__ void cp16(unsigned dst, const void* src) {
    asm volatile("cp.async.cg.shared.global [%0], [%1], 16;" ::"r"(dst), "l"(src));
}
#define CP_COMMIT() asm volatile("cp.async.commit_group;" ::: "memory")
template <int N>
__device__ __forceinline__ void cp_wait() {
    asm volatile("cp.async.wait_group %0;" ::"n"(N) : "memory");
}

// ---------------------------------------------------------------------------
// Merged one-time prep: blocks [0,2048) build the fragment-major fp16 mask
// bias (0 / -32768); blocks [2048,6144) convert x / w_qkv / w_o to f16.
__global__ __launch_bounds__(256) void prep_all(const int* __restrict__ mask,
                                                const float* __restrict__ x,
                                                const float* __restrict__ w1,
                                                const float* __restrict__ w2) {
    int b = blockIdx.x;
    if (b < 2048) {
        int wbase = (b * 256 + threadIdx.x) * 4;
        unsigned wds[4];
#pragma unroll
        for (int q = 0; q < 4; ++q) {
            int wd = wbase + q;
            int r = wd >> 10, rem = wd & 1023;
            int j = rem >> 5, t4 = (rem >> 3) & 3, nt = rem & 7;
            int c = j * 64 + nt * 8 + 2 * t4;
            int m0 = __ldg(mask + (size_t)r * S_ + c);
            int m1 = __ldg(mask + (size_t)r * S_ + c + 1);
            wds[q] = (m0 ? 0u : 0xF800u) | (m1 ? 0u : 0xF8000000u);
        }
        *(uint4*)((unsigned*)g_Bh + wbase) = make_uint4(wds[0], wds[1], wds[2], wds[3]);
    } else {
        b -= 2048;
        const float* src;
        __half* dst;
        int base;
        if (b < 2048)      { src = x;  dst = g_Xh;  base = b; }
        else if (b < 3584) { src = w1; dst = g_W1h; base = b - 2048; }
        else               { src = w2; dst = g_W2h; base = b - 3584; }
        int i = (base * 256 + threadIdx.x) * 8;
        float4 v0 = *(const float4*)(src + i);
        float4 v1 = *(const float4*)(src + i + 4);
        uint4 u;
        u.x = h2(v0.x, v0.y); u.y = h2(v0.z, v0.w);
        u.z = h2(v1.x, v1.y); u.w = h2(v1.z, v1.w);
        *(uint4*)(dst + i) = u;
    }
}

// ---------------------------------------------------------------------------
// fp16 tensor-core GEMM (round-13 form: LDG register prefetch, double-buffered
// smem, ONE barrier/iter). Block 128x128, BK=64 halves, 8 warps, stride 72.
// MODE 0: A=g_Xh, N=3072, scatter half2 into g_Qh/g_Kh/g_Vh (Q pre-scaled).
// MODE 1: A=g_Ch, N=1024, out f32.
// ---------------------------------------------------------------------------
template <int MODE>
__global__ __launch_bounds__(256, 2) void gemm_tc(const __half* __restrict__ A,
                                                  const __half* __restrict__ W,
                                                  const float* __restrict__ bias,
                                                  float* __restrict__ out) {
    extern __shared__ __half shh[];
    __half* As = shh;                  // [2][128][72]
    __half* Bs = shh + 2 * 128 * 72;   // [2][128][72]

    const int m0 = blockIdx.y * 128;
    const int n0 = blockIdx.x * 128;
    const int t = threadIdx.x;
    const int w = t >> 5;
    const int lane = t & 31;
    const int g = lane >> 2;
    const int t4 = lane & 3;
    const int wm = (w >> 2) * 64;
    const int wn = (w & 3) * 32;

    const int seg = t & 7;
    const int r0 = t >> 3;

    const unsigned sA = smem_u32(As);
    const unsigned sB = smem_u32(Bs);
    const unsigned BUF = 128 * 72 * 2;
    const unsigned aoff = (wm + (lane & 15)) * 144 + (lane >> 4) * 16;
    const unsigned boff = (wn + (lane & 15)) * 144 + (lane >> 4) * 16;

    uint4 ar[4], br[4];
#pragma unroll
    for (int i = 0; i < 4; ++i) {
        int row = r0 + i * 32;
        ar[i] = *(const uint4*)(A + (size_t)(m0 + row) * D_ + seg * 8);
        br[i] = *(const uint4*)(W + (size_t)(n0 + row) * D_ + seg * 8);
    }
#pragma unroll
    for (int i = 0; i < 4; ++i) {
        int row = r0 + i * 32;
        *(uint4*)&As[row * 72 + seg * 8] = ar[i];
        *(uint4*)&Bs[row * 72 + seg * 8] = br[i];
    }
    __syncthreads();

    float acc[4][4][4];
#pragma unroll
    for (int mt = 0; mt < 4; ++mt)
#pragma unroll
        for (int nt = 0; nt < 4; ++nt)
#pragma unroll
            for (int i = 0; i < 4; ++i) acc[mt][nt][i] = 0.0f;

    for (int k0 = 0; k0 < 16; ++k0) {
        const unsigned bA = sA + (k0 & 1) * BUF;
        const unsigned bB = sB + (k0 & 1) * BUF;
        if (k0 < 15) {
            int ko = (k0 + 1) * 64;
#pragma unroll
            for (int i = 0; i < 4; ++i) {
                int row = r0 + i * 32;
                ar[i] = *(const uint4*)(A + (size_t)(m0 + row) * D_ + ko + seg * 8);
                br[i] = *(const uint4*)(W + (size_t)(n0 + row) * D_ + ko + seg * 8);
            }
        }
#pragma unroll
        for (int ks = 0; ks < 4; ++ks) {
            unsigned a[4][4];
#pragma unroll
            for (int mt = 0; mt < 4; ++mt)
                ldsm4(a[mt], bA + aoff + mt * 16 * 144 + ks * 32);
#pragma unroll
            for (int p = 0; p < 2; ++p) {
                unsigned bb[4];
                ldsm4(bb, bB + boff + p * 16 * 144 + ks * 32);
#pragma unroll
                for (int mt = 0; mt < 4; ++mt) {
                    mma_f16(acc[mt][2 * p], a[mt][0], a[mt][1], a[mt][2], a[mt][3],
                            bb[0], bb[2]);
                    mma_f16(acc[mt][2 * p + 1], a[mt][0], a[mt][1], a[mt][2], a[mt][3],
                            bb[1], bb[3]);
                }
            }
        }
        if (k0 < 15) {
            __half* Ad = As + ((k0 + 1) & 1) * 128 * 72;
            __half* Bd = Bs + ((k0 + 1) & 1) * 128 * 72;
#pragma unroll
            for (int i = 0; i < 4; ++i) {
                int row = r0 + i * 32;
                *(uint4*)&Ad[row * 72 + seg * 8] = ar[i];
                *(uint4*)&Bd[row * 72 + seg * 8] = br[i];
            }
        }
        __syncthreads();
    }

#pragma unroll
    for (int mt = 0; mt < 4; ++mt) {
#pragma unroll
        for (int nt = 0; nt < 4; ++nt) {
            int ncol = n0 + wn + nt * 8 + 2 * t4;
            float bx = __ldg(&bias[ncol]);
            float by = __ldg(&bias[ncol + 1]);
#pragma unroll
            for (int rr = 0; rr < 2; ++rr) {
                int m = m0 + wm + mt * 16 + g + rr * 8;
                float vx = acc[mt][nt][rr * 2] + bx;
                float vy = acc[mt][nt][rr * 2 + 1] + by;
                if (MODE == 0) {
                    int bb2 = m >> 11, ss = m & 2047;
                    int h = ncol / 192;
                    int rem = ncol - h * 192;
                    int part = rem >> 6;
                    int d = rem & 63;
                    if (part == 0) { vx *= SCALE2; vy *= SCALE2; }
                    size_t dst = (((size_t)(bb2 * H_ + h)) * S_ + ss) * HD_ + d;
                    __half* dstp = (part == 0 ? g_Qh : (part == 1 ? g_Kh : g_Vh));
                    __half2 hv = __floats2half2_rn(vx, vy);
                    *(__half2*)&dstp[dst] = hv;
                } else {
                    *(float2*)&out[(size_t)m * D_ + ncol] = make_float2(vx, vy);
                }
            }
        }
    }
}

// ---------------------------------------------------------------------------
// Flash attention (round-13 structure) + warp-uniform rescale skip:
// when no row in the warp saw a new max, alpha == 1.0 exactly, so the
// o-rescale and the two ex2 are a bit-exact identity -> skip behind ballot.
// ---------------------------------------------------------------------------
__global__ __launch_bounds__(256, 2) void attn_tc() {
    extern __shared__ __half shh[];
    __half* Qs = shh;                   // [128][72]
    __half* Ks = shh + 128 * 72;        // [4][64][72]
    __half* Vs = Ks + 4 * 64 * 72;      // [4][64][72]

    const int bh = blockIdx.y;
    const int q0 = blockIdx.x * 128;
    const int t = threadIdx.x;
    const int w = t >> 5;
    const int lane = t & 31;
    const int g = lane >> 2;
    const int t4 = lane & 3;

    const size_t base = (size_t)bh * (S_ * HD_);
    const __half* Qg = g_Qh + base;
    const __half* Kg = g_Kh + base;
    const __half* Vg = g_Vh + base;

    const int seg = t & 7;
    const int r0 = t >> 3;

    const unsigned sQ = smem_u32(Qs);
    const unsigned sK = smem_u32(Ks);
    const unsigned sV = smem_u32(Vs);
    const unsigned KBUF = 64 * 72 * 2;
    const unsigned qoff = (w * 16 + (lane & 15)) * 144 + (lane >> 4) * 16;
    const unsigned koff = (lane & 15) * 144 + (lane >> 4) * 16;

    // stage Q
#pragma unroll
    for (int i = 0; i < 4; ++i) {
        int row = r0 + i * 32;
        *(uint4*)&Qs[row * 72 + seg * 8] =
            *(const uint4*)(Qg + (size_t)(q0 + row) * HD_ + seg * 8);
    }
    // cp.async stage K/V tiles 0,1 into ring stages 0,1
#pragma unroll
    for (int tile = 0; tile < 2; ++tile) {
#pragma unroll
        for (int i = 0; i < 2; ++i) {
            int row = r0 + i * 32;
            cp16(sK + tile * KBUF + (row * 72 + seg * 8) * 2,
                 Kg + ((size_t)tile * 64 + row) * HD_ + seg * 8);
            cp16(sV + tile * KBUF + (row * 72 + seg * 8) * 2,
                 Vg + ((size_t)tile * 64 + row) * HD_ + seg * 8);
        }
        CP_COMMIT();
    }
    __syncthreads();

    // Q fragments register-resident (loop-invariant)
    unsigned qa[4][4];
#pragma unroll
    for (int ks = 0; ks < 4; ++ks) ldsm4(qa[ks], sQ + qoff + ks * 32);

    const int qrow0 = q0 + w * 16 + g;
    const int qrow1 = qrow0 + 8;
    const unsigned* bq0 = (const unsigned*)(g_Bh + (size_t)qrow0 * S_) + t4 * 8;
    const unsigned* bq1 = (const unsigned*)(g_Bh + (size_t)qrow1 * S_) + t4 * 8;

    float o[8][4];
#pragma unroll
    for (int nt = 0; nt < 8; ++nt)
#pragma unroll
        for (int i = 0; i < 4; ++i) o[nt][i] = 0.0f;
    float m0s = -INFINITY, m1s = -INFINITY, l0 = 0.0f, l1 = 0.0f;

    for (int jj = 0; jj < 32; jj += 2) {
        cp_wait<0>();
        __syncthreads();
        const unsigned ph = (unsigned)(jj & 2);
#pragma unroll
        for (int u = 0; u < 2; ++u) {
            const int j = jj + u;
            const unsigned bK = sK + (ph + u) * KBUF;
            const unsigned bV = sV + (ph + u) * KBUF;
            if (j + 2 < 32) {
                const __half* Kn = Kg + (size_t)(j + 2) * 64 * HD_;
                const __half* Vn = Vg + (size_t)(j + 2) * 64 * HD_;
                unsigned dK = sK + ((ph + u + 2) & 3) * KBUF;
                unsigned dV = sV + ((ph + u + 2) & 3) * KBUF;
#pragma unroll
                for (int i = 0; i < 2; ++i) {
                    int row = r0 + i * 32;
                    cp16(dK + (row * 72 + seg * 8) * 2, Kn + (size_t)row * HD_ + seg * 8);
                    cp16(dV + (row * 72 + seg * 8) * 2, Vn + (size_t)row * HD_ + seg * 8);
                }
                CP_COMMIT();
            }
            // mask bias (fragment-major): 4 LDG.128
            uint4 ba = __ldg((const uint4*)(bq0 + j * 32));
            uint4 bb4 = __ldg((const uint4*)(bq0 + j * 32 + 4));
            uint4 bc = __ldg((const uint4*)(bq1 + j * 32));
            uint4 bd = __ldg((const uint4*)(bq1 + j * 32 + 4));
            unsigned bw0[8] = {ba.x, ba.y, ba.z, ba.w, bb4.x, bb4.y, bb4.z, bb4.w};
            unsigned bw1[8] = {bc.x, bc.y, bc.z, bc.w, bd.x, bd.y, bd.z, bd.w};

            // S = Q @ K^T
            float sc[8][4];
#pragma unroll
            for (int nt = 0; nt < 8; ++nt)
#pragma unroll
                for (int i = 0; i < 4; ++i) sc[nt][i] = 0.0f;
#pragma unroll
            for (int ks = 0; ks < 4; ++ks) {
#pragma unroll
                for (int p = 0; p < 4; ++p) {
                    unsigned kb[4];
                    ldsm4(kb, bK + koff + p * 16 * 144 + ks * 32);
                    mma_f16(sc[2 * p], qa[ks][0], qa[ks][1], qa[ks][2], qa[ks][3],
                            kb[0], kb[2]);
                    mma_f16(sc[2 * p + 1], qa[ks][0], qa[ks][1], qa[ks][2], qa[ks][3],
                            kb[1], kb[3]);
                }
            }

            // running max over unmasked logits
            float mx0 = -INFINITY, mx1 = -INFINITY;
#pragma unroll
            for (int nt = 0; nt < 8; ++nt) {
                mx0 = fmaxf(mx0, fmaxf(sc[nt][0], sc[nt][1]));
                mx1 = fmaxf(mx1, fmaxf(sc[nt][2], sc[nt][3]));
            }
            mx0 = fmaxf(mx0, __shfl_xor_sync(0xffffffffu, mx0, 1));
            mx0 = fmaxf(mx0, __shfl_xor_sync(0xffffffffu, mx0, 2));
            mx1 = fmaxf(mx1, __shfl_xor_sync(0xffffffffu, mx1, 1));
            mx1 = fmaxf(mx1, __shfl_xor_sync(0xffffffffu, mx1, 2));
            float mn0 = fmaxf(m0s, mx0), mn1 = fmaxf(m1s, mx1);

            // warp-uniform rescale skip: alpha==1.0 exactly when no new max,
            // so skipping is bit-identical.
            bool upd = (mn0 != m0s) || (mn1 != m1s);
            if (__ballot_sync(0xffffffffu, upd)) {
                float al0 = ex2(m0s - mn0), al1 = ex2(m1s - mn1);
                m0s = mn0; m1s = mn1;
                l0 *= al0; l1 *= al1;
#pragma unroll
                for (int nt = 0; nt < 8; ++nt) {
                    o[nt][0] *= al0; o[nt][1] *= al0;
                    o[nt][2] *= al1; o[nt][3] *= al1;
                }
            }

            // pack -> +(-mn) -> +bias -> exp, all in half2 domain
            unsigned mneg0 = h2(-mn0, -mn0);
            unsigned mneg1 = h2(-mn1, -mn1);
            unsigned ph_lo[8], ph_hi[8];
#pragma unroll
            for (int nt = 0; nt < 8; ++nt) {
                ph_lo[nt] = ex2h2(hadd2u(hadd2u(h2(sc[nt][0], sc[nt][1]), mneg0), bw0[nt]));
                ph_hi[nt] = ex2h2(hadd2u(hadd2u(h2(sc[nt][2], sc[nt][3]), mneg1), bw1[nt]));
            }

            // row sums via ones-matrix mma
            float rs[4] = {0.0f, 0.0f, 0.0f, 0.0f};
#pragma unroll
            for (int kt = 0; kt < 4; ++kt)
                mma_f16(rs, ph_lo[2 * kt], ph_hi[2 * kt], ph_lo[2 * kt + 1],
                        ph_hi[2 * kt + 1], ONESH2, ONESH2);
            l0 += rs[0];
            l1 += rs[2];

            // O += P @ V
#pragma unroll
            for (int kt = 0; kt < 4; ++kt) {
                unsigned a0 = ph_lo[2 * kt];
                unsigned a1 = ph_hi[2 * kt];
                unsigned a2 = ph_lo[2 * kt + 1];
                unsigned a3 = ph_hi[2 * kt + 1];
#pragma unroll
                for (int q = 0; q < 4; ++q) {
                    unsigned vb[4];
                    ldsm4t(vb, bV + koff + kt * 16 * 144 + q * 32);
                    mma_f16(o[2 * q], a0, a1, a2, a3, vb[0], vb[1]);
                    mma_f16(o[2 * q + 1], a0, a1, a2, a3, vb[2], vb[3]);
                }
            }
        }
    }

    // epilogue
    const int bb = bh >> 4;
    const int h = bh & 15;
    float inv0 = 1.0f / l0, inv1 = 1.0f / l1;
#pragma unroll
    for (int nt = 0; nt < 8; ++nt) {
        int dcol = h * 64 + nt * 8 + 2 * t4;
        size_t rr0 = ((size_t)bb * S_ + qrow0) * D_ + dcol;
        size_t rr1 = ((size_t)bb * S_ + qrow1) * D_ + dcol;
        __half2 v0 = __floats2half2_rn(o[nt][0] * inv0, o[nt][1] * inv0);
        __half2 v1 = __floats2half2_rn(o[nt][2] * inv1, o[nt][3] * inv1);
        *(__half2*)&g_Ch[rr0] = v0;
        *(__half2*)&g_Ch[rr1] = v1;
    }
}

// ---------------------------------------------------------------------------
extern "C" void kernel_launch(void* const* d_in, const int* in_sizes, int n_in,
                              void* d_out, int out_size) {
    const float* x     = (const float*)d_in[0];
    const int*   mask  = (const int*)d_in[1];
    const float* w_qkv = (const float*)d_in[2];
    const float* b_qkv = (const float*)d_in[3];
    const float* w_o   = (const float*)d_in[4];
    const float* b_o   = (const float*)d_in[5];
    float* out = (float*)d_out;

    const int gemm_smem = 4 * 128 * 72 * 2;              // 73728
    const int attn_smem = (128 * 72 + 8 * 64 * 72) * 2;  // 92160

    cudaFuncSetAttribute(gemm_tc<0>, cudaFuncAttributeMaxDynamicSharedMemorySize, gemm_smem);
    cudaFuncSetAttribute(gemm_tc<1>, cudaFuncAttributeMaxDynamicSharedMemorySize, gemm_smem);
    cudaFuncSetAttribute(attn_tc, cudaFuncAttributeMaxDynamicSharedMemorySize, attn_smem);

    // 0) one-time prep (mask bias + f16 converts, single launch)
    prep_all<<<6144, 256>>>(mask, x, w_qkv, w_o);

    __half *dXh, *dW1h, *dW2h, *dCh;
    cudaGetSymbolAddress((void**)&dXh, g_Xh);
    cudaGetSymbolAddress((void**)&dW1h, g_W1h);
    cudaGetSymbolAddress((void**)&dW2h, g_W2h);
    cudaGetSymbolAddress((void**)&dCh, g_Ch);

    // 1) QKV projection
    gemm_tc<0><<<dim3(3072 / 128, 4096 / 128), 256, gemm_smem>>>(dXh, dW1h, b_qkv, nullptr);

    // 2) flash attention
    attn_tc<<<dim3(S_ / 128, B_ * H_), 256, attn_smem>>>();

    // 3) output projection
    gemm_tc<1><<<dim3(1024 / 128, 4096 / 128), 256, gemm_smem>>>(dCh, dW2h, b_o, out);
}

// round 16
// speedup vs baseline: 1.0443x; 1.0132x over previous
#include <cuda_runtime.h>
#include <cuda_fp16.h>
#include <math.h>
#include <cstdint>

#define B_ 2
#define S_ 2048
#define D_ 1024
#define H_ 16
#define HD_ 64
#define SCALE2 0.1803368801111204f
#define ONESH2 0x3C003C00u

// Scratch (device globals: allocation-free rule)
__device__ __half g_Qh[B_ * H_ * S_ * HD_];
__device__ __half g_Kh[B_ * H_ * S_ * HD_];
__device__ __half g_Vh[B_ * H_ * S_ * HD_];
__device__ __half g_Ch[B_ * S_ * D_];
__device__ __half g_Xh[B_ * S_ * D_];
__device__ __half g_W1h[3 * D_ * D_];
__device__ __half g_W2h[D_ * D_];
// mask bias, fragment-major: word(r, j, t4, nt) at r*1024 + j*32 + t4*8 + nt
__device__ __half g_Bh[S_ * S_];
// row-block completion flags for attn -> out-proj fusion (32 blocks of 128 rows)
__device__ int g_flag[32];

__device__ __forceinline__ float ex2(float x) {
    float y;
    asm("ex2.approx.f32 %0, %1;" : "=f"(y) : "f"(x));
    return y;
}
__device__ __forceinline__ unsigned ex2h2(unsigned x) {
    unsigned y;
    asm("ex2.approx.f16x2 %0, %1;" : "=r"(y) : "r"(x));
    return y;
}
__device__ __forceinline__ unsigned h2(float a, float b) {
    __half2 h = __floats2half2_rn(a, b);
    return *(unsigned*)&h;
}
__device__ __forceinline__ unsigned hadd2u(unsigned a, unsigned b) {
    __half2 r = __hadd2(*(__half2*)&a, *(__half2*)&b);
    return *(unsigned*)&r;
}
__device__ __forceinline__ void mma_f16(float c[4], unsigned a0, unsigned a1,
                                        unsigned a2, unsigned a3,
                                        unsigned b0, unsigned b1) {
    asm volatile(
        "mma.sync.aligned.m16n8k16.row.col.f32.f16.f16.f32 "
        "{%0,%1,%2,%3}, {%4,%5,%6,%7}, {%8,%9}, {%0,%1,%2,%3};"
        : "+f"(c[0]), "+f"(c[1]), "+f"(c[2]), "+f"(c[3])
        : "r"(a0), "r"(a1), "r"(a2), "r"(a3), "r"(b0), "r"(b1));
}
__device__ __forceinline__ unsigned smem_u32(const void* p) {
    return (unsigned)__cvta_generic_to_shared(p);
}
__device__ __forceinline__ void ldsm4(unsigned r[4], unsigned addr) {
    asm volatile(
        "ldmatrix.sync.aligned.m8n8.x4.shared.b16 {%0,%1,%2,%3}, [%4];"
        : "=r"(r[0]), "=r"(r[1]), "=r"(r[2]), "=r"(r[3]) : "r"(addr));
}
__device__ __forceinline__ void ldsm4t(unsigned r[4], unsigned addr) {
    asm volatile(
        "ldmatrix.sync.aligned.m8n8.x4.trans.shared.b16 {%0,%1,%2,%3}, [%4];"
        : "=r"(r[0]), "=r"(r[1]), "=r"(r[2]), "=r"(r[3]) : "r"(addr));
}
__device__ __forceinline__ void cp16(unsigned dst, const void* src) {
    asm volatile("cp.async.cg.shared.global [%0], [%1], 16;" ::"r"(dst), "l"(src));
}
#define CP_COMMIT() asm volatile("cp.async.commit_group;" ::: "memory")
template <int N>
__device__ __forceinline__ void cp_wait() {
    asm volatile("cp.async.wait_group %0;" ::"n"(N) : "memory");
}

// ---------------------------------------------------------------------------
// Merged one-time prep: flag reset + fragment-major fp16 mask bias +
// f32->f16 converts for x / w_qkv / w_o.
__global__ __launch_bounds__(256) void prep_all(const int* __restrict__ mask,
                                                const float* __restrict__ x,
                                                const float* __restrict__ w1,
                                                const float* __restrict__ w2) {
    int b = blockIdx.x;
    if (b == 0 && threadIdx.x < 32) g_flag[threadIdx.x] = 0;
    if (b < 2048) {
        int wbase = (b * 256 + threadIdx.x) * 4;
        unsigned wds[4];
#pragma unroll
        for (int q = 0; q < 4; ++q) {
            int wd = wbase + q;
            int r = wd >> 10, rem = wd & 1023;
            int j = rem >> 5, t4 = (rem >> 3) & 3, nt = rem & 7;
            int c = j * 64 + nt * 8 + 2 * t4;
            int m0 = __ldg(mask + (size_t)r * S_ + c);
            int m1 = __ldg(mask + (size_t)r * S_ + c + 1);
            wds[q] = (m0 ? 0u : 0xF800u) | (m1 ? 0u : 0xF8000000u);
        }
        *(uint4*)((unsigned*)g_Bh + wbase) = make_uint4(wds[0], wds[1], wds[2], wds[3]);
    } else {
        b -= 2048;
        const float* src;
        __half* dst;
        int base;
        if (b < 2048)      { src = x;  dst = g_Xh;  base = b; }
        else if (b < 3584) { src = w1; dst = g_W1h; base = b - 2048; }
        else               { src = w2; dst = g_W2h; base = b - 3584; }
        int i = (base * 256 + threadIdx.x) * 8;
        float4 v0 = *(const float4*)(src + i);
        float4 v1 = *(const float4*)(src + i + 4);
        uint4 u;
        u.x = h2(v0.x, v0.y); u.y = h2(v0.z, v0.w);
        u.z = h2(v1.x, v1.y); u.w = h2(v1.z, v1.w);
        *(uint4*)(dst + i) = u;
    }
}

// ---------------------------------------------------------------------------
// QKV projection GEMM (round-15 form, unchanged math). Block 128x128, BK=64,
// LDG register prefetch, double-buffered smem, one barrier/iter.
// ---------------------------------------------------------------------------
__global__ __launch_bounds__(256, 2) void gemm_qkv(const __half* __restrict__ A,
                                                   const __half* __restrict__ W,
                                                   const float* __restrict__ bias) {
    extern __shared__ __half shh[];
    __half* As = shh;
    __half* Bs = shh + 2 * 128 * 72;

    const int m0 = blockIdx.y * 128;
    const int n0 = blockIdx.x * 128;
    const int t = threadIdx.x;
    const int w = t >> 5;
    const int lane = t & 31;
    const int g = lane >> 2;
    const int t4 = lane & 3;
    const int wm = (w >> 2) * 64;
    const int wn = (w & 3) * 32;
    const int seg = t & 7;
    const int r0 = t >> 3;

    const unsigned sA = smem_u32(As);
    const unsigned sB = smem_u32(Bs);
    const unsigned BUF = 128 * 72 * 2;
    const unsigned aoff = (wm + (lane & 15)) * 144 + (lane >> 4) * 16;
    const unsigned boff = (wn + (lane & 15)) * 144 + (lane >> 4) * 16;

    uint4 ar[4], br[4];
#pragma unroll
    for (int i = 0; i < 4; ++i) {
        int row = r0 + i * 32;
        ar[i] = *(const uint4*)(A + (size_t)(m0 + row) * D_ + seg * 8);
        br[i] = *(const uint4*)(W + (size_t)(n0 + row) * D_ + seg * 8);
    }
#pragma unroll
    for (int i = 0; i < 4; ++i) {
        int row = r0 + i * 32;
        *(uint4*)&As[row * 72 + seg * 8] = ar[i];
        *(uint4*)&Bs[row * 72 + seg * 8] = br[i];
    }
    __syncthreads();

    float acc[4][4][4];
#pragma unroll
    for (int mt = 0; mt < 4; ++mt)
#pragma unroll
        for (int nt = 0; nt < 4; ++nt)
#pragma unroll
            for (int i = 0; i < 4; ++i) acc[mt][nt][i] = 0.0f;

    for (int k0 = 0; k0 < 16; ++k0) {
        const unsigned bA = sA + (k0 & 1) * BUF;
        const unsigned bB = sB + (k0 & 1) * BUF;
        if (k0 < 15) {
            int ko = (k0 + 1) * 64;
#pragma unroll
            for (int i = 0; i < 4; ++i) {
                int row = r0 + i * 32;
                ar[i] = *(const uint4*)(A + (size_t)(m0 + row) * D_ + ko + seg * 8);
                br[i] = *(const uint4*)(W + (size_t)(n0 + row) * D_ + ko + seg * 8);
            }
        }
#pragma unroll
        for (int ks = 0; ks < 4; ++ks) {
            unsigned a[4][4];
#pragma unroll
            for (int mt = 0; mt < 4; ++mt)
                ldsm4(a[mt], bA + aoff + mt * 16 * 144 + ks * 32);
#pragma unroll
            for (int p = 0; p < 2; ++p) {
                unsigned bb[4];
                ldsm4(bb, bB + boff + p * 16 * 144 + ks * 32);
#pragma unroll
                for (int mt = 0; mt < 4; ++mt) {
                    mma_f16(acc[mt][2 * p], a[mt][0], a[mt][1], a[mt][2], a[mt][3],
                            bb[0], bb[2]);
                    mma_f16(acc[mt][2 * p + 1], a[mt][0], a[mt][1], a[mt][2], a[mt][3],
                            bb[1], bb[3]);
                }
            }
        }
        if (k0 < 15) {
            __half* Ad = As + ((k0 + 1) & 1) * 128 * 72;
            __half* Bd = Bs + ((k0 + 1) & 1) * 128 * 72;
#pragma unroll
            for (int i = 0; i < 4; ++i) {
                int row = r0 + i * 32;
                *(uint4*)&Ad[row * 72 + seg * 8] = ar[i];
                *(uint4*)&Bd[row * 72 + seg * 8] = br[i];
            }
        }
        __syncthreads();
    }

#pragma unroll
    for (int mt = 0; mt < 4; ++mt) {
#pragma unroll
        for (int nt = 0; nt < 4; ++nt) {
            int ncol = n0 + wn + nt * 8 + 2 * t4;
            float2 bv = __ldg((const float2*)&bias[ncol]);
#pragma unroll
            for (int rr = 0; rr < 2; ++rr) {
                int m = m0 + wm + mt * 16 + g + rr * 8;
                float vx = acc[mt][nt][rr * 2] + bv.x;
                float vy = acc[mt][nt][rr * 2 + 1] + bv.y;
                int bb2 = m >> 11, ss = m & 2047;
                int h = ncol / 192;
                int rem = ncol - h * 192;
                int part = rem >> 6;
                int d = rem & 63;
                if (part == 0) { vx *= SCALE2; vy *= SCALE2; }
                size_t dst = (((size_t)(bb2 * H_ + h)) * S_ + ss) * HD_ + d;
                __half* dstp = (part == 0 ? g_Qh : (part == 1 ? g_Kh : g_Vh));
                __half2 hv = __floats2half2_rn(vx, vy);
                *(__half2*)&dstp[dst] = hv;
            }
        }
    }
}

// ---------------------------------------------------------------------------
// FUSED attention + output projection. Blocks 0..511: attention (bh=bid>>4,
// q0=(bid&15)*128); on completion: threadfence + atomicAdd(g_flag[rowblock]).
// Blocks 512..767: output GEMM m-tile; spins until its row-block's 16 attn
// CTAs (all heads) have flagged. Deadlock-free: 256 gemm blocks < 296 slots.
// ---------------------------------------------------------------------------
__global__ __launch_bounds__(256, 2) void attn_out(const float* __restrict__ bias,
                                                   float* __restrict__ out) {
    extern __shared__ __half shh[];
    const int bid = blockIdx.x;
    const int t = threadIdx.x;
    const int w = t >> 5;
    const int lane = t & 31;
    const int g = lane >> 2;
    const int t4 = lane & 3;
    const int seg = t & 7;
    const int r0 = t >> 3;

    if (bid < 512) {
        // ================= attention =================
        __half* Qs = shh;                   // [128][72]
        __half* Ks = shh + 128 * 72;        // [4][64][72]
        __half* Vs = Ks + 4 * 64 * 72;      // [4][64][72]

        const int bh = bid >> 4;
        const int q0blk = bid & 15;
        const int q0 = q0blk * 128;

        const size_t base = (size_t)bh * (S_ * HD_);
        const __half* Qg = g_Qh + base;
        const __half* Kg = g_Kh + base;
        const __half* Vg = g_Vh + base;

        const unsigned sQ = smem_u32(Qs);
        const unsigned sK = smem_u32(Ks);
        const unsigned sV = smem_u32(Vs);
        const unsigned KBUF = 64 * 72 * 2;
        const unsigned qoff = (w * 16 + (lane & 15)) * 144 + (lane >> 4) * 16;
        const unsigned koff = (lane & 15) * 144 + (lane >> 4) * 16;

#pragma unroll
        for (int i = 0; i < 4; ++i) {
            int row = r0 + i * 32;
            *(uint4*)&Qs[row * 72 + seg * 8] =
                *(const uint4*)(Qg + (size_t)(q0 + row) * HD_ + seg * 8);
        }
#pragma unroll
        for (int tile = 0; tile < 2; ++tile) {
#pragma unroll
            for (int i = 0; i < 2; ++i) {
                int row = r0 + i * 32;
                cp16(sK + tile * KBUF + (row * 72 + seg * 8) * 2,
                     Kg + ((size_t)tile * 64 + row) * HD_ + seg * 8);
                cp16(sV + tile * KBUF + (row * 72 + seg * 8) * 2,
                     Vg + ((size_t)tile * 64 + row) * HD_ + seg * 8);
            }
            CP_COMMIT();
        }
        __syncthreads();

        unsigned qa[4][4];
#pragma unroll
        for (int ks = 0; ks < 4; ++ks) ldsm4(qa[ks], sQ + qoff + ks * 32);

        const int qrow0 = q0 + w * 16 + g;
        const int qrow1 = qrow0 + 8;
        const unsigned* bq0 = (const unsigned*)(g_Bh + (size_t)qrow0 * S_) + t4 * 8;
        const unsigned* bq1 = (const unsigned*)(g_Bh + (size_t)qrow1 * S_) + t4 * 8;

        float o[8][4];
#pragma unroll
        for (int nt = 0; nt < 8; ++nt)
#pragma unroll
            for (int i = 0; i < 4; ++i) o[nt][i] = 0.0f;
        float m0s = -INFINITY, m1s = -INFINITY, l0 = 0.0f, l1 = 0.0f;

        for (int jj = 0; jj < 32; jj += 2) {
            cp_wait<0>();
            __syncthreads();
            const unsigned ph = (unsigned)(jj & 2);
#pragma unroll
            for (int u = 0; u < 2; ++u) {
                const int j = jj + u;
                const unsigned bK = sK + (ph + u) * KBUF;
                const unsigned bV = sV + (ph + u) * KBUF;
                if (j + 2 < 32) {
                    const __half* Kn = Kg + (size_t)(j + 2) * 64 * HD_;
                    const __half* Vn = Vg + (size_t)(j + 2) * 64 * HD_;
                    unsigned dK = sK + ((ph + u + 2) & 3) * KBUF;
                    unsigned dV = sV + ((ph + u + 2) & 3) * KBUF;
#pragma unroll
                    for (int i = 0; i < 2; ++i) {
                        int row = r0 + i * 32;
                        cp16(dK + (row * 72 + seg * 8) * 2, Kn + (size_t)row * HD_ + seg * 8);
                        cp16(dV + (row * 72 + seg * 8) * 2, Vn + (size_t)row * HD_ + seg * 8);
                    }
                    CP_COMMIT();
                }
                uint4 ba = __ldg((const uint4*)(bq0 + j * 32));
                uint4 bb4 = __ldg((const uint4*)(bq0 + j * 32 + 4));
                uint4 bc = __ldg((const uint4*)(bq1 + j * 32));
                uint4 bd = __ldg((const uint4*)(bq1 + j * 32 + 4));
                unsigned bw0[8] = {ba.x, ba.y, ba.z, ba.w, bb4.x, bb4.y, bb4.z, bb4.w};
                unsigned bw1[8] = {bc.x, bc.y, bc.z, bc.w, bd.x, bd.y, bd.z, bd.w};

                float sc[8][4];
#pragma unroll
                for (int nt = 0; nt < 8; ++nt)
#pragma unroll
                    for (int i = 0; i < 4; ++i) sc[nt][i] = 0.0f;
#pragma unroll
                for (int ks = 0; ks < 4; ++ks) {
#pragma unroll
                    for (int p = 0; p < 4; ++p) {
                        unsigned kb[4];
                        ldsm4(kb, bK + koff + p * 16 * 144 + ks * 32);
                        mma_f16(sc[2 * p], qa[ks][0], qa[ks][1], qa[ks][2], qa[ks][3],
                                kb[0], kb[2]);
                        mma_f16(sc[2 * p + 1], qa[ks][0], qa[ks][1], qa[ks][2], qa[ks][3],
                                kb[1], kb[3]);
                    }
                }

                float mx0 = -INFINITY, mx1 = -INFINITY;
#pragma unroll
                for (int nt = 0; nt < 8; ++nt) {
                    mx0 = fmaxf(mx0, fmaxf(sc[nt][0], sc[nt][1]));
                    mx1 = fmaxf(mx1, fmaxf(sc[nt][2], sc[nt][3]));
                }
                mx0 = fmaxf(mx0, __shfl_xor_sync(0xffffffffu, mx0, 1));
                mx0 = fmaxf(mx0, __shfl_xor_sync(0xffffffffu, mx0, 2));
                mx1 = fmaxf(mx1, __shfl_xor_sync(0xffffffffu, mx1, 1));
                mx1 = fmaxf(mx1, __shfl_xor_sync(0xffffffffu, mx1, 2));
                float mn0 = fmaxf(m0s, mx0), mn1 = fmaxf(m1s, mx1);

                bool upd = (mn0 != m0s) || (mn1 != m1s);
                if (__ballot_sync(0xffffffffu, upd)) {
                    float al0 = ex2(m0s - mn0), al1 = ex2(m1s - mn1);
                    m0s = mn0; m1s = mn1;
                    l0 *= al0; l1 *= al1;
#pragma unroll
                    for (int nt = 0; nt < 8; ++nt) {
                        o[nt][0] *= al0; o[nt][1] *= al0;
                        o[nt][2] *= al1; o[nt][3] *= al1;
                    }
                }

                unsigned mneg0 = h2(-mn0, -mn0);
                unsigned mneg1 = h2(-mn1, -mn1);
                unsigned ph_lo[8], ph_hi[8];
#pragma unroll
                for (int nt = 0; nt < 8; ++nt) {
                    ph_lo[nt] = ex2h2(hadd2u(hadd2u(h2(sc[nt][0], sc[nt][1]), mneg0), bw0[nt]));
                    ph_hi[nt] = ex2h2(hadd2u(hadd2u(h2(sc[nt][2], sc[nt][3]), mneg1), bw1[nt]));
                }

                float rs[4] = {0.0f, 0.0f, 0.0f, 0.0f};
#pragma unroll
                for (int kt = 0; kt < 4; ++kt)
                    mma_f16(rs, ph_lo[2 * kt], ph_hi[2 * kt], ph_lo[2 * kt + 1],
                            ph_hi[2 * kt + 1], ONESH2, ONESH2);
                l0 += rs[0];
                l1 += rs[2];

#pragma unroll
                for (int kt = 0; kt < 4; ++kt) {
                    unsigned a0 = ph_lo[2 * kt];
                    unsigned a1 = ph_hi[2 * kt];
                    unsigned a2 = ph_lo[2 * kt + 1];
                    unsigned a3 = ph_hi[2 * kt + 1];
#pragma unroll
                    for (int q = 0; q < 4; ++q) {
                        unsigned vb[4];
                        ldsm4t(vb, bV + koff + kt * 16 * 144 + q * 32);
                        mma_f16(o[2 * q], a0, a1, a2, a3, vb[0], vb[1]);
                        mma_f16(o[2 * q + 1], a0, a1, a2, a3, vb[2], vb[3]);
                    }
                }
            }
        }

        // epilogue + completion flag
        const int bb = bh >> 4;
        const int h = bh & 15;
        float inv0 = 1.0f / l0, inv1 = 1.0f / l1;
#pragma unroll
        for (int nt = 0; nt < 8; ++nt) {
            int dcol = h * 64 + nt * 8 + 2 * t4;
            size_t rr0 = ((size_t)bb * S_ + qrow0) * D_ + dcol;
            size_t rr1 = ((size_t)bb * S_ + qrow1) * D_ + dcol;
            __half2 v0 = __floats2half2_rn(o[nt][0] * inv0, o[nt][1] * inv0);
            __half2 v1 = __floats2half2_rn(o[nt][2] * inv1, o[nt][3] * inv1);
            *(__half2*)&g_Ch[rr0] = v0;
            *(__half2*)&g_Ch[rr1] = v1;
        }
        __threadfence();
        __syncthreads();
        if (t == 0) atomicAdd(&g_flag[bb * 16 + q0blk], 1);
    } else {
        // ================= output projection =================
        __half* As = shh;
        __half* Bs = shh + 2 * 128 * 72;

        const int bidg = bid - 512;
        const int m0 = (bidg >> 3) * 128;
        const int n0 = (bidg & 7) * 128;
        const int rb = bidg >> 3;   // row-block 0..31

        // wait for the 16 attn CTAs (all heads) of this row-block
        if (t == 0) {
            while (atomicAdd(&g_flag[rb], 0) < 16) __nanosleep(64);
            __threadfence();
        }
        __syncthreads();

        const __half* A = g_Ch;
        const __half* W = g_W2h;
        const int wm = (w >> 2) * 64;
        const int wn = (w & 3) * 32;

        const unsigned sA = smem_u32(As);
        const unsigned sB = smem_u32(Bs);
        const unsigned BUF = 128 * 72 * 2;
        const unsigned aoff = (wm + (lane & 15)) * 144 + (lane >> 4) * 16;
        const unsigned boff = (wn + (lane & 15)) * 144 + (lane >> 4) * 16;

        uint4 ar[4], br[4];
#pragma unroll
        for (int i = 0; i < 4; ++i) {
            int row = r0 + i * 32;
            ar[i] = *(const uint4*)(A + (size_t)(m0 + row) * D_ + seg * 8);
            br[i] = *(const uint4*)(W + (size_t)(n0 + row) * D_ + seg * 8);
        }
#pragma unroll
        for (int i = 0; i < 4; ++i) {
            int row = r0 + i * 32;
            *(uint4*)&As[row * 72 + seg * 8] = ar[i];
            *(uint4*)&Bs[row * 72 + seg * 8] = br[i];
        }
        __syncthreads();

        float acc[4][4][4];
#pragma unroll
        for (int mt = 0; mt < 4; ++mt)
#pragma unroll
            for (int nt = 0; nt < 4; ++nt)
#pragma unroll
                for (int i = 0; i < 4; ++i) acc[mt][nt][i] = 0.0f;

        for (int k0 = 0; k0 < 16; ++k0) {
            const unsigned bA = sA + (k0 & 1) * BUF;
            const unsigned bB = sB + (k0 & 1) * BUF;
            if (k0 < 15) {
                int ko = (k0 + 1) * 64;
#pragma unroll
                for (int i = 0; i < 4; ++i) {
                    int row = r0 + i * 32;
                    ar[i] = *(const uint4*)(A + (size_t)(m0 + row) * D_ + ko + seg * 8);
                    br[i] = *(const uint4*)(W + (size_t)(n0 + row) * D_ + ko + seg * 8);
                }
            }
#pragma unroll
            for (int ks = 0; ks < 4; ++ks) {
                unsigned a[4][4];
#pragma unroll
                for (int mt = 0; mt < 4; ++mt)
                    ldsm4(a[mt], bA + aoff + mt * 16 * 144 + ks * 32);
#pragma unroll
                for (int p = 0; p < 2; ++p) {
                    unsigned bb[4];
                    ldsm4(bb, bB + boff + p * 16 * 144 + ks * 32);
#pragma unroll
                    for (int mt = 0; mt < 4; ++mt) {
                        mma_f16(acc[mt][2 * p], a[mt][0], a[mt][1], a[mt][2], a[mt][3],
                                bb[0], bb[2]);
                        mma_f16(acc[mt][2 * p + 1], a[mt][0], a[mt][1], a[mt][2], a[mt][3],
                                bb[1], bb[3]);
                    }
                }
            }
            if (k0 < 15) {
                __half* Ad = As + ((k0 + 1) & 1) * 128 * 72;
                __half* Bd = Bs + ((k0 + 1) & 1) * 128 * 72;
#pragma unroll
                for (int i = 0; i < 4; ++i) {
                    int row = r0 + i * 32;
                    *(uint4*)&Ad[row * 72 + seg * 8] = ar[i];
                    *(uint4*)&Bd[row * 72 + seg * 8] = br[i];
                }
            }
            __syncthreads();
        }

#pragma unroll
        for (int mt = 0; mt < 4; ++mt) {
#pragma unroll
            for (int nt = 0; nt < 4; ++nt) {
                int ncol = n0 + wn + nt * 8 + 2 * t4;
                float2 bv = __ldg((const float2*)&bias[ncol]);
#pragma unroll
                for (int rr = 0; rr < 2; ++rr) {
                    int m = m0 + wm + mt * 16 + g + rr * 8;
                    float vx = acc[mt][nt][rr * 2] + bv.x;
                    float vy = acc[mt][nt][rr * 2 + 1] + bv.y;
                    *(float2*)&out[(size_t)m * D_ + ncol] = make_float2(vx, vy);
                }
            }
        }
    }
}

// ---------------------------------------------------------------------------
extern "C" void kernel_launch(void* const* d_in, const int* in_sizes, int n_in,
                              void* d_out, int out_size) {
    const float* x     = (const float*)d_in[0];
    const int*   mask  = (const int*)d_in[1];
    const float* w_qkv = (const float*)d_in[2];
    const float* b_qkv = (const float*)d_in[3];
    const float* w_o   = (const float*)d_in[4];
    const float* b_o   = (const float*)d_in[5];
    float* out = (float*)d_out;

    const int gemm_smem  = 4 * 128 * 72 * 2;              // 73728
    const int fused_smem = (128 * 72 + 8 * 64 * 72) * 2;  // 92160

    cudaFuncSetAttribute(gemm_qkv, cudaFuncAttributeMaxDynamicSharedMemorySize, gemm_smem);
    cudaFuncSetAttribute(attn_out, cudaFuncAttributeMaxDynamicSharedMemorySize, fused_smem);

    __half *dXh, *dW1h;
    cudaGetSymbolAddress((void**)&dXh, g_Xh);
    cudaGetSymbolAddress((void**)&dW1h, g_W1h);

    // 0) one-time prep (flag reset + mask bias + f16 converts)
    prep_all<<<6144, 256>>>(mask, x, w_qkv, w_o);

    // 1) QKV projection
    gemm_qkv<<<dim3(3072 / 128, 4096 / 128), 256, gemm_smem>>>(dXh, dW1h, b_qkv);

    // 2) fused attention + output projection (flag-ordered)
    attn_out<<<768, 256, fused_smem>>>(b_o, out);
}